// round 14
// baseline (speedup 1.0000x reference)
#include <cuda_runtime.h>
#include <cuda_fp16.h>
#include <cstdint>
#include <math.h>

#define Bn 4
#define Hn 256
#define Wn 320
#define HWn (Hn*Wn)          // 81920
#define NPIX (Bn*HWn)        // 327680
#define NSn 256

// ---------------- device-global scratch --------------------------------------
__device__ __align__(16) char  g_p0[(size_t)NPIX*320];   // [pix][80ch hi|80ch lo] fp16
__device__ __align__(16) char  g_p1[(size_t)NPIX*320];   // same, ch0-31 = rh
__device__ __align__(16) char  g_p2[(size_t)NPIX*128];   // [pix][32ch hi|32ch lo] fp16 (h)
__device__ __align__(16) char  g_t2h[(size_t)NPIX*256];  // [pix][64ch hi|64ch lo] fp16 (t2)
__device__ __align__(16) __half g_wb[175104];            // conv weights, FRAGMENT layout
__device__ __align__(16) __half g_w3[32768];             // dh3 weights (softmax staging layout)
__device__ float g_z [(size_t)NPIX*32];

// ---------------- helpers -----------------------------------------------------
__device__ __forceinline__ uint32_t smem_u32(const void* p){
    uint32_t a;
    asm("{ .reg .u64 t; cvta.to.shared.u64 t, %1; cvt.u32.u64 %0, t; }" : "=r"(a) : "l"(p));
    return a;
}
__device__ __forceinline__ void ldm_x4(uint32_t* r, uint32_t addr){
    asm volatile("ldmatrix.sync.aligned.m8n8.x4.shared.b16 {%0,%1,%2,%3}, [%4];"
        : "=r"(r[0]), "=r"(r[1]), "=r"(r[2]), "=r"(r[3]) : "r"(addr));
}
__device__ __forceinline__ void mma16(float4& d, const uint32_t* a, uint32_t b0, uint32_t b1){
    asm volatile("mma.sync.aligned.m16n8k16.row.col.f32.f16.f16.f32 "
        "{%0,%1,%2,%3},{%4,%5,%6,%7},{%8,%9},{%0,%1,%2,%3};"
        : "+f"(d.x), "+f"(d.y), "+f"(d.z), "+f"(d.w)
        : "r"(a[0]), "r"(a[1]), "r"(a[2]), "r"(a[3]), "r"(b0), "r"(b1));
}
__device__ __forceinline__ float sigmoidf_(float v){ return 1.f/(1.f+__expf(-v)); }

// ---------------- pre-kernel 1: input planes ----------------------------------
__global__ void __launch_bounds__(128) prep_inputs(
    const float* __restrict__ hidden,
    const float* __restrict__ ndep,
    const float* __restrict__ corr)
{
    __shared__ __half sm[128*160];
    int tid = threadIdx.x;
    int g0 = blockIdx.x*128;
    int b = g0 / HWn, hwb = g0 - b*HWn;
    int hw = hwb + tid;

    #pragma unroll 1
    for (int ch = 0; ch < 80; ++ch){
        float v = 0.f;
        if (ch < 32)       v = hidden[(size_t)(b*32+ch)*HWn + hw];
        else if (ch == 32) v = ndep[(size_t)b*HWn + hw];
        else if (ch < 65)  v = corr[(size_t)(b*32+ch-33)*HWn + hw];
        __half h = __float2half_rn(v);
        sm[tid*160 + ch]      = h;
        sm[tid*160 + 80 + ch] = __float2half_rn(v - __half2float(h));
    }
    __syncthreads();

    uint4* dst0 = (uint4*)(g_p0 + (size_t)g0*320);
    const uint4* src = (const uint4*)sm;
    #pragma unroll
    for (int i = 0; i < 20; ++i) dst0[tid + i*128] = src[tid + i*128];

    for (int e = tid; e < 128*12; e += 128){
        int p = e / 12, u = e - p*12;
        int hb = (u < 6) ? (32 + u*8) : (112 + (u-6)*8);
        *(uint4*)(g_p1 + (size_t)(g0+p)*320 + hb*2) = *(const uint4*)(sm + p*160 + hb);
    }
}

// ---------------- pre-kernel 2: weights in mma-FRAGMENT layout -----------------
__global__ void prep_weights(
    const float* __restrict__ zw, const float* __restrict__ rw,
    const float* __restrict__ qw,
    const float* __restrict__ d1w, const float* __restrict__ c1w,
    const float* __restrict__ w3)
{
    int idx = blockIdx.x*256 + threadIdx.x;
    if (idx < 175104){
        int kc, rem, t, cc, sect;
        __half* dst;
        if (idx < 92160){
            kc = idx >> 11; rem = idx & 2047;
            t = kc/5; cc = kc - t*5; sect = 0;
            dst = g_wb + idx;
        } else if (idx < 138240){
            int p = idx - 92160;
            kc = p >> 10; rem = p & 1023;
            t = kc/5; cc = kc - t*5; sect = 1;
            dst = g_wb + idx;
        } else {
            int p = idx - 138240;
            kc = p >> 11; rem = p & 2047;
            t = kc >> 1; cc = kc & 1; sect = 2;
            dst = g_wb + idx;
        }
        int fi   = rem >> 8;
        int lane = (rem >> 3) & 31;
        int e    = rem & 7;
        int ntp  = fi >> 1, hl = fi & 1;
        int r    = e >> 1,  lsb = e & 1;
        int n_loc = ntp*16 + ((r & 2) << 2) + (lane >> 2);
        int k_loc = ((r & 1) << 3) + ((lane & 3) << 1) + lsb;
        int ch = cc*16 + k_loc;
        float v = 0.f;
        if (sect == 0){
            if (ch < 65) v = (n_loc < 32) ? zw[n_loc*585 + ch*9 + t]
                                          : rw[(n_loc-32)*585 + ch*9 + t];
        } else if (sect == 1){
            if (ch < 65) v = qw[n_loc*585 + ch*9 + t];
        } else {
            v = (n_loc < 32) ? d1w[n_loc*288 + ch*9 + t]
                             : c1w[(n_loc-32)*288 + ch*9 + t];
        }
        __half h = __float2half_rn(v);
        *dst = hl ? __float2half_rn(v - __half2float(h)) : h;
    } else if (idx < 191488){
        int j = idx - 175104;
        int kc = j >> 12, rem = j & 4095, n = rem >> 4, ci = rem & 15;
        float v = w3[n*64 + kc*16 + ci];
        __half h = __float2half_rn(v);
        __half* dh = g_w3 + kc*8192 + n*16 + ci;
        dh[0]    = h;
        dh[4096] = __float2half_rn(v - __half2float(h));
    }
}

// ---------------- strip-resident conv: 8 warps, 16 px/warp, barrier-free ------
template<int MODE>
__global__ void __launch_bounds__(256, (MODE == 1) ? 3 : 2) conv_mma(
    const float* __restrict__ biasA,
    const float* __restrict__ biasB,
    const float* __restrict__ hidden,
    const float* __restrict__ dh2w,
    const float* __restrict__ ch2w,
    const float* __restrict__ ch2b,
    float* __restrict__ o0,
    float* __restrict__ o1,
    float* __restrict__ o2)
{
    constexpr int N      = (MODE == 1) ? 32 : 64;
    constexpr int NCHK   = (MODE == 2) ? 18 : 45;
    constexpr int DIL    = (MODE == 2) ? 2 : 1;
    constexpr int SW     = 16 + 2*DIL;
    constexpr int SH     = 8 + 2*DIL;
    constexpr int PLANEB = (MODE == 2) ? 128 : 320;
    constexpr int ROWB   = (MODE == 2) ? 144 : 336;
    constexpr int LO_OFF = (MODE == 2) ? 64 : 160;
    constexpr int STRIPB = SH*SW*ROWB;
    constexpr int WOFF   = (MODE == 0) ? 0 : (MODE == 1) ? 92160 : 138240;
    constexpr int CU4    = N*32/8;
    constexpr int NFR    = (N/16)*2;

    extern __shared__ char sm[];
    char*  strip = sm;
    float* dh2s  = (float*)(sm + STRIPB);
    float* A1    = (float*)sm;

    int tid = threadIdx.x, lane = tid & 31, w = tid >> 5;   // w in 0..7
    int r = lane >> 2, cq = lane & 3;
    int bx0 = blockIdx.x*16, by0 = blockIdx.y*8, b = blockIdx.z;

    const char* plane = (MODE == 0) ? g_p0 : (MODE == 1) ? g_p1 : g_p2;

    constexpr int PU = PLANEB/16;
    constexpr int UT = SH*SW*PU;
    for (int e = tid; e < UT; e += 256){
        int sp = e/PU, u = e - sp*PU;
        int sy = sp/SW, sx = sp - sy*SW;
        int y = by0 - DIL + sy, x = bx0 - DIL + sx;
        uint4 v = make_uint4(0u,0u,0u,0u);
        if (y >= 0 && y < Hn && x >= 0 && x < Wn)
            v = __ldg((const uint4*)(plane + ((size_t)(b*HWn + y*Wn + x))*PLANEB) + u);
        *(uint4*)(strip + sp*ROWB + u*16) = v;
    }
    if (MODE == 2){
        for (int e = tid; e < 2048; e += 256){
            int ic = e >> 6, oc = e & 63;
            dh2s[e] = dh2w[oc*32 + ic];
        }
    }
    __syncthreads();     // the ONLY barrier before the epilogue

    uint32_t stripS = smem_u32(strip);
    uint32_t apix;
    {
        int p = w*16 + (lane & 15);
        apix = stripS + (uint32_t)(((p>>4)*SW + (p&15))*ROWB) + ((uint32_t)(lane>>4) << 4);
    }

    float4 acc[N/8];
    #pragma unroll
    for (int nt = 0; nt < N/8; ++nt)
        acc[nt] = make_float4(0.f,0.f,0.f,0.f);

    const uint4* Bg = (const uint4*)(g_wb + WOFF) + lane;

    auto loadB = [&](int kc, uint4* buf){
        const uint4* p = Bg + kc*CU4;
        #pragma unroll
        for (int fi = 0; fi < NFR; ++fi) buf[fi] = __ldg(p + fi*32);
    };
    auto doChunk = [&](int kc, const uint4* cur){
        int t  = (MODE == 2) ? (kc >> 1) : (kc/5);
        int cc = (MODE == 2) ? (kc & 1)  : (kc - t*5);
        int j3 = t/3, jx = t - j3*3;
        uint32_t tap = (uint32_t)((j3*SW + jx)*DIL*ROWB) + (uint32_t)cc*32;
        uint32_t ah[4], al[4];
        ldm_x4(ah, apix + tap);
        ldm_x4(al, apix + tap + LO_OFF);
        #pragma unroll
        for (int ntp = 0; ntp < N/16; ++ntp){
            uint4 qh = cur[ntp*2], ql = cur[ntp*2+1];
            mma16(acc[ntp*2  ], ah, qh.x, qh.y);
            mma16(acc[ntp*2  ], ah, ql.x, ql.y);
            mma16(acc[ntp*2  ], al, qh.x, qh.y);
            mma16(acc[ntp*2+1], ah, qh.z, qh.w);
            mma16(acc[ntp*2+1], ah, ql.z, ql.w);
            mma16(acc[ntp*2+1], al, qh.z, qh.w);
        }
    };

    {
        uint4 bufA[NFR], bufB[NFR];
        loadB(0, bufA);
        int kc = 0;
        while (true){
            if (kc + 1 < NCHK) loadB(kc + 1, bufB);
            doChunk(kc, bufA);
            if (++kc >= NCHK) break;
            if (kc + 1 < NCHK) loadB(kc + 1, bufA);
            doChunk(kc, bufB);
            if (++kc >= NCHK) break;
        }
    }
    __syncthreads();    // strip free for A1 overlay

    // ---------------- epilogues ----------------
    if (MODE == 0){
        #pragma unroll
        for (int half = 0; half < 2; ++half){
            int p = w*16 + r + 8*half;
            int hwp = (by0 + (p>>4))*Wn + bx0 + (p&15);
            #pragma unroll
            for (int nt = 0; nt < 8; ++nt){
                int col = nt*8 + cq*2;
                float v0 = half ? acc[nt].z : acc[nt].x;
                float v1 = half ? acc[nt].w : acc[nt].y;
                if (nt < 4){
                    o0[((size_t)(b*32 + col  ))*HWn + hwp] = sigmoidf_(v0 + __ldg(biasA + col));
                    o0[((size_t)(b*32 + col+1))*HWn + hwp] = sigmoidf_(v1 + __ldg(biasA + col+1));
                } else {
                    int oc = col - 32;
                    size_t i0 = ((size_t)(b*32 + oc  ))*HWn + hwp;
                    size_t i1 = ((size_t)(b*32 + oc+1))*HWn + hwp;
                    A1[p*33 + oc  ] = sigmoidf_(v0 + __ldg(biasB + oc  )) * __ldg(hidden + i0);
                    A1[p*33 + oc+1] = sigmoidf_(v1 + __ldg(biasB + oc+1)) * __ldg(hidden + i1);
                }
            }
        }
        __syncthreads();
        if (tid < 128){
            int p = tid;
            size_t g = (size_t)b*HWn + (by0 + (p>>4))*Wn + bx0 + (p&15);
            char* dst = g_p1 + g*320;
            #pragma unroll
            for (int u = 0; u < 4; ++u){
                __half hs[8], ls[8];
                #pragma unroll
                for (int i = 0; i < 8; ++i){
                    float v = A1[p*33 + u*8 + i];
                    __half h = __float2half_rn(v);
                    hs[i] = h;
                    ls[i] = __float2half_rn(v - __half2float(h));
                }
                *(uint4*)(dst + u*16)       = *(uint4*)hs;
                *(uint4*)(dst + 160 + u*16) = *(uint4*)ls;
            }
        }
    } else if (MODE == 1){
        #pragma unroll
        for (int half = 0; half < 2; ++half){
            int p = w*16 + r + 8*half;
            int hwp = (by0 + (p>>4))*Wn + bx0 + (p&15);
            #pragma unroll
            for (int nt = 0; nt < 4; ++nt){
                int col = nt*8 + cq*2;
                float v0 = half ? acc[nt].z : acc[nt].x;
                float v1 = half ? acc[nt].w : acc[nt].y;
                float q0 = tanhf(v0 + __ldg(biasA + col));
                float q1 = tanhf(v1 + __ldg(biasA + col+1));
                size_t i0 = ((size_t)(b*32 + col  ))*HWn + hwp;
                size_t i1 = ((size_t)(b*32 + col+1))*HWn + hwp;
                float z0 = g_z[i0], z1 = g_z[i1];
                float h0 = (1.f - z0)*__ldg(hidden + i0) + z0*q0;
                float h1 = (1.f - z1)*__ldg(hidden + i1) + z1*q1;
                o0[i0] = h0;
                o0[i1] = h1;
                A1[p*33 + col  ] = h0;
                A1[p*33 + col+1] = h1;
            }
        }
        __syncthreads();
        if (tid < 128){
            int p = tid;
            size_t g = (size_t)b*HWn + (by0 + (p>>4))*Wn + bx0 + (p&15);
            char* dst = g_p2 + g*128;
            #pragma unroll
            for (int u = 0; u < 4; ++u){
                __half hs[8], ls[8];
                #pragma unroll
                for (int i = 0; i < 8; ++i){
                    float v = A1[p*33 + u*8 + i];
                    __half h = __float2half_rn(v);
                    hs[i] = h;
                    ls[i] = __float2half_rn(v - __half2float(h));
                }
                *(uint4*)(dst + u*16)      = *(uint4*)hs;
                *(uint4*)(dst + 64 + u*16) = *(uint4*)ls;
            }
        }
    } else {
        float cb = __ldg(ch2b);
        float ps[2] = {0.f, 0.f};
        #pragma unroll
        for (int half = 0; half < 2; ++half){
            int p = w*16 + r + 8*half;
            #pragma unroll
            for (int nt = 0; nt < 8; ++nt){
                int col = nt*8 + cq*2;
                float v0 = half ? acc[nt].z : acc[nt].x;
                float v1 = half ? acc[nt].w : acc[nt].y;
                v0 = fmaxf(v0, 0.f);
                v1 = fmaxf(v1, 0.f);
                if (nt < 4){
                    A1[p*33 + col  ] = v0;
                    A1[p*33 + col+1] = v1;
                } else {
                    ps[half] = fmaf(v0, __ldg(ch2w + col-32),
                               fmaf(v1, __ldg(ch2w + col-31), ps[half]));
                }
            }
        }
        #pragma unroll
        for (int half = 0; half < 2; ++half){
            float pp = ps[half];
            pp += __shfl_xor_sync(0xffffffffu, pp, 1);
            pp += __shfl_xor_sync(0xffffffffu, pp, 2);
            if (cq == 0){
                int p = w*16 + r + 8*half;
                size_t g = (size_t)b*HWn + (by0 + (p>>4))*Wn + bx0 + (p&15);
                float cs = cb + pp;
                o2[g] = cs;
                o1[g] = sigmoidf_(cs);
            }
        }
        __syncthreads();
        if (tid < 128){
            float a[32];
            #pragma unroll
            for (int ic = 0; ic < 32; ++ic) a[ic] = A1[tid*33 + ic];
            float t2[64];
            #pragma unroll
            for (int i = 0; i < 64; ++i) t2[i] = 0.f;
            #pragma unroll
            for (int ic = 0; ic < 32; ++ic){
                float vv = a[ic];
                const float4* wr = (const float4*)(dh2s + ic*64);
                #pragma unroll
                for (int q4 = 0; q4 < 16; ++q4){
                    float4 w4 = wr[q4];
                    t2[q4*4+0] = fmaf(vv, w4.x, t2[q4*4+0]);
                    t2[q4*4+1] = fmaf(vv, w4.y, t2[q4*4+1]);
                    t2[q4*4+2] = fmaf(vv, w4.z, t2[q4*4+2]);
                    t2[q4*4+3] = fmaf(vv, w4.w, t2[q4*4+3]);
                }
            }
            size_t g = (size_t)b*HWn + (by0 + (tid>>4))*Wn + bx0 + (tid&15);
            char* dst = g_t2h + g*256;
            #pragma unroll
            for (int u = 0; u < 8; ++u){
                __half hs[8], ls[8];
                #pragma unroll
                for (int i = 0; i < 8; ++i){
                    float v = fmaxf(t2[u*8 + i], 0.f);
                    __half h = __float2half_rn(v);
                    hs[i] = h;
                    ls[i] = __float2half_rn(v - __half2float(h));
                }
                *(uint4*)(dst + u*16)       = *(uint4*)hs;
                *(uint4*)(dst + 128 + u*16) = *(uint4*)ls;
            }
        }
    }
}

// ---------------- softmax head v2 + coalesced prob store ----------------------
__global__ void __launch_bounds__(256) softmax_head(
    const float* __restrict__ b3,
    float* __restrict__ prob,
    float* __restrict__ nd)
{
    extern __shared__ char sm[];
    char*  t2s  = sm;                          // 64 x 272B
    char*  bbuf = sm + 17408;                  // 2 x 24576
    float* b3s  = (float*)(sm + 66560);        // 256
    float* rs_s = (float*)(sm + 67584);        // 64
    float* logits = (float*)sm;                // overlay: 64 x 260 fp32

    int tid = threadIdx.x, lane = tid & 31, w = tid >> 5;
    int g0 = blockIdx.x * 64;
    int b  = g0 / HWn, hw0 = g0 - b*HWn;

    {
        const uint4* src = (const uint4*)(g_t2h + (size_t)g0*256);
        #pragma unroll
        for (int e = tid; e < 1024; e += 256){
            int p = e >> 4, u = e & 15;
            *(uint4*)(t2s + p*272 + u*16) = __ldg(src + e);
        }
    }
    b3s[tid] = b3[tid];

    auto stageB = [&](int kc, int s){
        const __half* base = g_w3 + kc*8192;
        char* dst = bbuf + s*24576;
        #pragma unroll
        for (int e = tid; e < 1024; e += 256){
            int hl = e >> 9, rem = e & 511, n = rem >> 1, part = rem & 1;
            uint4 v = *(const uint4*)(base + hl*4096 + n*16 + part*8);
            *(uint4*)(dst + hl*12288 + n*48 + part*16) = v;
        }
    };
    stageB(0, 0);
    stageB(1, 1);
    __syncthreads();

    int mi = w >> 1, ng = w & 1;
    uint32_t t2S = smem_u32(t2s);
    uint32_t bS  = smem_u32(bbuf);

    float4 acc[16];
    #pragma unroll
    for (int i = 0; i < 16; ++i) acc[i] = make_float4(0.f,0.f,0.f,0.f);

    #pragma unroll
    for (int ck = 0; ck < 4; ++ck){
        uint32_t slot = bS + (uint32_t)(ck & 1)*24576;
        int rowA = mi*16 + (lane & 15);
        uint32_t aoff = t2S + (uint32_t)(rowA*272 + ck*32) + ((uint32_t)(lane>>4) << 4);
        uint32_t ah[4], al[4];
        ldm_x4(ah, aoff);
        ldm_x4(al, aoff + 128);
        #pragma unroll
        for (int nt16 = 0; nt16 < 8; ++nt16){
            int rowB = ng*128 + nt16*16 + (lane & 7) + ((lane >> 4) << 3);
            uint32_t boff = slot + (uint32_t)(rowB*48 + ((lane >> 3) & 1)*16);
            uint32_t bh[4], bl[4];
            ldm_x4(bh, boff);
            ldm_x4(bl, boff + 12288);
            mma16(acc[nt16*2  ], ah, bh[0], bh[1]);
            mma16(acc[nt16*2  ], ah, bl[0], bl[1]);
            mma16(acc[nt16*2  ], al, bh[0], bh[1]);
            mma16(acc[nt16*2+1], ah, bh[2], bh[3]);
            mma16(acc[nt16*2+1], ah, bl[2], bl[3]);
            mma16(acc[nt16*2+1], al, bh[2], bh[3]);
        }
        __syncthreads();
        if (ck + 2 < 4) stageB(ck + 2, ck & 1);
    }

    {
        int r = lane >> 2, cq = lane & 3;
        #pragma unroll
        for (int nt = 0; nt < 16; ++nt){
            int col = ng*128 + nt*8 + cq*2;
            int row0 = mi*16 + r;
            float bb0 = b3s[col], bb1 = b3s[col+1];
            logits[row0*260 + col]     = acc[nt].x + bb0;
            logits[row0*260 + col+1]   = acc[nt].y + bb1;
            logits[(row0+8)*260 + col]   = acc[nt].z + bb0;
            logits[(row0+8)*260 + col+1] = acc[nt].w + bb1;
        }
    }
    __syncthreads();

    int px = (w << 3) + (lane >> 2);
    int cg = lane & 3;
    float* lrow = logits + px*260 + cg;

    float m = -3.4e38f; int am = 255;
    #pragma unroll
    for (int j = 0; j < 64; ++j){
        float v = lrow[j*4];
        int oc = cg + j*4;
        if (v > m || (v == m && oc < am)) { m = v; am = oc; }
    }
    #pragma unroll
    for (int d = 1; d < 4; d <<= 1){
        float om = __shfl_xor_sync(0xffffffffu, m, d);
        int   oa = __shfl_xor_sync(0xffffffffu, am, d);
        if (om > m || (om == m && oa < am)) { m = om; am = oa; }
    }

    float s = 0.f;
    #pragma unroll
    for (int j = 0; j < 64; ++j){
        float e = __expf(lrow[j*4] - m);
        lrow[j*4] = e;
        s += e;
    }
    #pragma unroll
    for (int d = 1; d < 4; d <<= 1) s += __shfl_xor_sync(0xffffffffu, s, d);
    float rS = 1.f / s;

    int lo = am - 4, hi = am + 4;
    int ocl = lo < 0 ? 0 : lo;
    int och = hi > 255 ? 255 : hi;
    float num = 0.f, den = 0.f;
    #pragma unroll
    for (int j = 0; j < 64; ++j){
        int oc = cg + j*4;
        if (oc >= ocl && oc <= och){
            float pv = lrow[j*4] * rS;
            float mult = 1.f;
            if (oc == 0   && lo < 0)   mult += (float)(-lo);
            if (oc == 255 && hi > 255) mult += (float)(hi - 255);
            num = fmaf(mult * (float)oc, pv, num);
            den = fmaf(mult, pv, den);
        }
    }
    #pragma unroll
    for (int d = 1; d < 4; d <<= 1){
        num += __shfl_xor_sync(0xffffffffu, num, d);
        den += __shfl_xor_sync(0xffffffffu, den, d);
    }
    if (cg == 0){
        nd[g0 + px] = (num / (1e-6f + den)) * (1.0f / 255.0f);
        rs_s[px] = rS;
    }
    __syncthreads();

    {
        float* pbase = prob + (size_t)b*NSn*HWn + hw0;
        #pragma unroll 8
        for (int e = tid; e < 16384; e += 256){
            int oc2 = e >> 6, p2 = e & 63;
            pbase[(size_t)oc2*HWn + p2] = logits[p2*260 + oc2] * rs_s[p2];
        }
    }
}

// ---------------- launch ------------------------------------------------------
extern "C" void kernel_launch(void* const* d_in, const int* in_sizes, int n_in,
                              void* d_out, int out_size)
{
    const float* hidden  = (const float*)d_in[0];
    const float* ndep    = (const float*)d_in[1];
    const float* corr    = (const float*)d_in[2];
    const float* convz_w = (const float*)d_in[3];
    const float* convz_b = (const float*)d_in[4];
    const float* convr_w = (const float*)d_in[5];
    const float* convr_b = (const float*)d_in[6];
    const float* convq_w = (const float*)d_in[7];
    const float* convq_b = (const float*)d_in[8];
    const float* dh1_w   = (const float*)d_in[9];
    const float* dh2_w   = (const float*)d_in[10];
    const float* dh3_w   = (const float*)d_in[11];
    const float* dh3_b   = (const float*)d_in[12];
    const float* ch1_w   = (const float*)d_in[13];
    const float* ch2_w   = (const float*)d_in[14];
    const float* ch2_b   = (const float*)d_in[15];

    float* out = (float*)d_out;
    float* out_h     = out;
    float* out_nd    = out_h  + (size_t)NPIX*32;
    float* out_prob  = out_nd + NPIX;
    float* out_conf  = out_prob + (size_t)NPIX*256;
    float* out_conf0 = out_conf + NPIX;

    float* zbuf;  cudaGetSymbolAddress((void**)&zbuf,  g_z);

    const int SMEM_M0 = 10*18*336;               // 60480
    const int SMEM_M1 = 10*18*336;               // 60480
    const int SMEM_M2 = 12*20*144 + 8192;        // 42752
    const int SMEM_SMAX = 66560 + 1024 + 256;    // 67840

    cudaFuncSetAttribute(conv_mma<0>, cudaFuncAttributeMaxDynamicSharedMemorySize, SMEM_M0);
    cudaFuncSetAttribute(conv_mma<1>, cudaFuncAttributeMaxDynamicSharedMemorySize, SMEM_M1);
    cudaFuncSetAttribute(conv_mma<2>, cudaFuncAttributeMaxDynamicSharedMemorySize, SMEM_M2);
    cudaFuncSetAttribute(softmax_head, cudaFuncAttributeMaxDynamicSharedMemorySize, SMEM_SMAX);

    prep_inputs<<<NPIX/128, 128>>>(hidden, ndep, corr);
    prep_weights<<<(191488 + 255)/256, 256>>>(convz_w, convr_w, convq_w, dh1_w, ch1_w, dh3_w);

    dim3 blk(256);
    dim3 grd(Wn/16, Hn/8, Bn);

    conv_mma<0><<<grd, blk, SMEM_M0>>>(convz_b, convr_b, hidden,
                                       nullptr, nullptr, nullptr,
                                       zbuf, nullptr, nullptr);
    conv_mma<1><<<grd, blk, SMEM_M1>>>(convq_b, nullptr, hidden,
                                       nullptr, nullptr, nullptr,
                                       out_h, nullptr, nullptr);
    conv_mma<2><<<grd, blk, SMEM_M2>>>(nullptr, nullptr, nullptr,
                                       dh2_w, ch2_w, ch2_b,
                                       nullptr, out_conf, out_conf0);
    softmax_head<<<NPIX/64, 256, SMEM_SMAX>>>(dh3_b, out_prob, out_nd);
}

// round 15
// speedup vs baseline: 1.0523x; 1.0523x over previous
#include <cuda_runtime.h>
#include <cuda_fp16.h>
#include <cstdint>
#include <math.h>

#define Bn 4
#define Hn 256
#define Wn 320
#define HWn (Hn*Wn)          // 81920
#define NPIX (Bn*HWn)        // 327680
#define NSn 256

// ---------------- device-global scratch --------------------------------------
__device__ __align__(16) char  g_p0[(size_t)NPIX*320];   // [pix][80ch hi|80ch lo] fp16
__device__ __align__(16) char  g_p1[(size_t)NPIX*320];   // same, ch0-31 = rh
__device__ __align__(16) char  g_p2[(size_t)NPIX*128];   // [pix][32ch hi|32ch lo] fp16 (h)
__device__ __align__(16) char  g_t2h[(size_t)NPIX*256];  // [pix][64ch hi|64ch lo] fp16 (t2)
__device__ __align__(16) __half g_wb[175104];            // conv weights, FRAGMENT layout
__device__ __align__(16) __half g_w3[32768];             // dh3 weights (softmax staging layout)
__device__ float g_z [(size_t)NPIX*32];

// ---------------- helpers -----------------------------------------------------
__device__ __forceinline__ uint32_t smem_u32(const void* p){
    uint32_t a;
    asm("{ .reg .u64 t; cvta.to.shared.u64 t, %1; cvt.u32.u64 %0, t; }" : "=r"(a) : "l"(p));
    return a;
}
__device__ __forceinline__ void ldm_x4(uint32_t* r, uint32_t addr){
    asm volatile("ldmatrix.sync.aligned.m8n8.x4.shared.b16 {%0,%1,%2,%3}, [%4];"
        : "=r"(r[0]), "=r"(r[1]), "=r"(r[2]), "=r"(r[3]) : "r"(addr));
}
__device__ __forceinline__ void mma16(float4& d, const uint32_t* a, uint32_t b0, uint32_t b1){
    asm volatile("mma.sync.aligned.m16n8k16.row.col.f32.f16.f16.f32 "
        "{%0,%1,%2,%3},{%4,%5,%6,%7},{%8,%9},{%0,%1,%2,%3};"
        : "+f"(d.x), "+f"(d.y), "+f"(d.z), "+f"(d.w)
        : "r"(a[0]), "r"(a[1]), "r"(a[2]), "r"(a[3]), "r"(b0), "r"(b1));
}
__device__ __forceinline__ float sigmoidf_(float v){ return 1.f/(1.f+__expf(-v)); }

// ---------------- pre-kernel 1: input planes ----------------------------------
__global__ void __launch_bounds__(128) prep_inputs(
    const float* __restrict__ hidden,
    const float* __restrict__ ndep,
    const float* __restrict__ corr)
{
    __shared__ __half sm[128*160];
    int tid = threadIdx.x;
    int g0 = blockIdx.x*128;
    int b = g0 / HWn, hwb = g0 - b*HWn;
    int hw = hwb + tid;

    #pragma unroll 1
    for (int ch = 0; ch < 80; ++ch){
        float v = 0.f;
        if (ch < 32)       v = hidden[(size_t)(b*32+ch)*HWn + hw];
        else if (ch == 32) v = ndep[(size_t)b*HWn + hw];
        else if (ch < 65)  v = corr[(size_t)(b*32+ch-33)*HWn + hw];
        __half h = __float2half_rn(v);
        sm[tid*160 + ch]      = h;
        sm[tid*160 + 80 + ch] = __float2half_rn(v - __half2float(h));
    }
    __syncthreads();

    uint4* dst0 = (uint4*)(g_p0 + (size_t)g0*320);
    const uint4* src = (const uint4*)sm;
    #pragma unroll
    for (int i = 0; i < 20; ++i) dst0[tid + i*128] = src[tid + i*128];

    for (int e = tid; e < 128*12; e += 128){
        int p = e / 12, u = e - p*12;
        int hb = (u < 6) ? (32 + u*8) : (112 + (u-6)*8);
        *(uint4*)(g_p1 + (size_t)(g0+p)*320 + hb*2) = *(const uint4*)(sm + p*160 + hb);
    }
}

// ---------------- pre-kernel 2: weights in mma-FRAGMENT layout -----------------
__global__ void prep_weights(
    const float* __restrict__ zw, const float* __restrict__ rw,
    const float* __restrict__ qw,
    const float* __restrict__ d1w, const float* __restrict__ c1w,
    const float* __restrict__ w3)
{
    int idx = blockIdx.x*256 + threadIdx.x;
    if (idx < 175104){
        int kc, rem, t, cc, sect;
        __half* dst;
        if (idx < 92160){
            kc = idx >> 11; rem = idx & 2047;
            t = kc/5; cc = kc - t*5; sect = 0;
            dst = g_wb + idx;
        } else if (idx < 138240){
            int p = idx - 92160;
            kc = p >> 10; rem = p & 1023;
            t = kc/5; cc = kc - t*5; sect = 1;
            dst = g_wb + idx;
        } else {
            int p = idx - 138240;
            kc = p >> 11; rem = p & 2047;
            t = kc >> 1; cc = kc & 1; sect = 2;
            dst = g_wb + idx;
        }
        int fi   = rem >> 8;
        int lane = (rem >> 3) & 31;
        int e    = rem & 7;
        int ntp  = fi >> 1, hl = fi & 1;
        int r    = e >> 1,  lsb = e & 1;
        int n_loc = ntp*16 + ((r & 2) << 2) + (lane >> 2);
        int k_loc = ((r & 1) << 3) + ((lane & 3) << 1) + lsb;
        int ch = cc*16 + k_loc;
        float v = 0.f;
        if (sect == 0){
            if (ch < 65) v = (n_loc < 32) ? zw[n_loc*585 + ch*9 + t]
                                          : rw[(n_loc-32)*585 + ch*9 + t];
        } else if (sect == 1){
            if (ch < 65) v = qw[n_loc*585 + ch*9 + t];
        } else {
            v = (n_loc < 32) ? d1w[n_loc*288 + ch*9 + t]
                             : c1w[(n_loc-32)*288 + ch*9 + t];
        }
        __half h = __float2half_rn(v);
        *dst = hl ? __float2half_rn(v - __half2float(h)) : h;
    } else if (idx < 191488){
        int j = idx - 175104;
        int kc = j >> 12, rem = j & 4095, n = rem >> 4, ci = rem & 15;
        float v = w3[n*64 + kc*16 + ci];
        __half h = __float2half_rn(v);
        __half* dh = g_w3 + kc*8192 + n*16 + ci;
        dh[0]    = h;
        dh[4096] = __float2half_rn(v - __half2float(h));
    }
}

// ---------------- strip-resident conv: barrier-free, 3-pass MMA ordering ------
template<int MODE>
__global__ void __launch_bounds__(128, 3) conv_mma(
    const float* __restrict__ biasA,
    const float* __restrict__ biasB,
    const float* __restrict__ hidden,
    const float* __restrict__ dh2w,
    const float* __restrict__ ch2w,
    const float* __restrict__ ch2b,
    float* __restrict__ o0,
    float* __restrict__ o1,
    float* __restrict__ o2)
{
    constexpr int N      = (MODE == 1) ? 32 : 64;
    constexpr int NCHK   = (MODE == 2) ? 18 : 45;
    constexpr int DIL    = (MODE == 2) ? 2 : 1;
    constexpr int SW     = 16 + 2*DIL;
    constexpr int SH     = 8 + 2*DIL;
    constexpr int PLANEB = (MODE == 2) ? 128 : 320;
    constexpr int ROWB   = (MODE == 2) ? 144 : 336;
    constexpr int LO_OFF = (MODE == 2) ? 64 : 160;
    constexpr int STRIPB = SH*SW*ROWB;
    constexpr int WOFF   = (MODE == 0) ? 0 : (MODE == 1) ? 92160 : 138240;
    constexpr int CU4    = N*32/8;
    constexpr int NFR    = (N/16)*2;

    extern __shared__ char sm[];
    char*  strip = sm;
    float* dh2s  = (float*)(sm + STRIPB);
    float* A1    = (float*)sm;

    int tid = threadIdx.x, lane = tid & 31, w = tid >> 5;
    int r = lane >> 2, cq = lane & 3;
    int bx0 = blockIdx.x*16, by0 = blockIdx.y*8, b = blockIdx.z;

    const char* plane = (MODE == 0) ? g_p0 : (MODE == 1) ? g_p1 : g_p2;

    constexpr int PU = PLANEB/16;
    constexpr int UT = SH*SW*PU;
    for (int e = tid; e < UT; e += 128){
        int sp = e/PU, u = e - sp*PU;
        int sy = sp/SW, sx = sp - sy*SW;
        int y = by0 - DIL + sy, x = bx0 - DIL + sx;
        uint4 v = make_uint4(0u,0u,0u,0u);
        if (y >= 0 && y < Hn && x >= 0 && x < Wn)
            v = __ldg((const uint4*)(plane + ((size_t)(b*HWn + y*Wn + x))*PLANEB) + u);
        *(uint4*)(strip + sp*ROWB + u*16) = v;
    }
    if (MODE == 2){
        for (int e = tid; e < 2048; e += 128){
            int ic = e >> 6, oc = e & 63;
            dh2s[e] = dh2w[oc*32 + ic];
        }
    }
    __syncthreads();     // the ONLY barrier before the epilogue

    uint32_t stripS = smem_u32(strip);
    uint32_t apix[2];
    #pragma unroll
    for (int mt = 0; mt < 2; ++mt){
        int p = w*32 + mt*16 + (lane & 15);
        apix[mt] = stripS + (uint32_t)(((p>>4)*SW + (p&15))*ROWB) + ((uint32_t)(lane>>4) << 4);
    }

    float4 acc[2][N/8];
    #pragma unroll
    for (int mt = 0; mt < 2; ++mt)
        #pragma unroll
        for (int nt = 0; nt < N/8; ++nt)
            acc[mt][nt] = make_float4(0.f,0.f,0.f,0.f);

    const uint4* Bg = (const uint4*)(g_wb + WOFF) + lane;

    auto loadB = [&](int kc, uint4* buf){
        const uint4* p = Bg + kc*CU4;
        #pragma unroll
        for (int fi = 0; fi < NFR; ++fi) buf[fi] = __ldg(p + fi*32);
    };
    // 3-pass ordering: every accumulator still receives its contributions
    // in the order hh -> hl -> lh (bit-identical to the sequential form),
    // but dependent MMAs on the same accumulator are now N/4 apart.
    auto doChunk = [&](int kc, const uint4* cur){
        int t  = (MODE == 2) ? (kc >> 1) : (kc/5);
        int cc = (MODE == 2) ? (kc & 1)  : (kc - t*5);
        int j3 = t/3, jx = t - j3*3;
        uint32_t tap = (uint32_t)((j3*SW + jx)*DIL*ROWB) + (uint32_t)cc*32;
        uint32_t ah[2][4], al[2][4];
        #pragma unroll
        for (int mt = 0; mt < 2; ++mt){
            ldm_x4(ah[mt], apix[mt] + tap);
            ldm_x4(al[mt], apix[mt] + tap + LO_OFF);
        }
        // pass 1: hi * Bhi
        #pragma unroll
        for (int ntp = 0; ntp < N/16; ++ntp){
            uint4 qh = cur[ntp*2];
            #pragma unroll
            for (int mt = 0; mt < 2; ++mt){
                mma16(acc[mt][ntp*2  ], ah[mt], qh.x, qh.y);
                mma16(acc[mt][ntp*2+1], ah[mt], qh.z, qh.w);
            }
        }
        // pass 2: hi * Blo
        #pragma unroll
        for (int ntp = 0; ntp < N/16; ++ntp){
            uint4 ql = cur[ntp*2+1];
            #pragma unroll
            for (int mt = 0; mt < 2; ++mt){
                mma16(acc[mt][ntp*2  ], ah[mt], ql.x, ql.y);
                mma16(acc[mt][ntp*2+1], ah[mt], ql.z, ql.w);
            }
        }
        // pass 3: lo * Bhi
        #pragma unroll
        for (int ntp = 0; ntp < N/16; ++ntp){
            uint4 qh = cur[ntp*2];
            #pragma unroll
            for (int mt = 0; mt < 2; ++mt){
                mma16(acc[mt][ntp*2  ], al[mt], qh.x, qh.y);
                mma16(acc[mt][ntp*2+1], al[mt], qh.z, qh.w);
            }
        }
    };

    {
        uint4 bufA[NFR], bufB[NFR];
        loadB(0, bufA);
        int kc = 0;
        while (true){
            if (kc + 1 < NCHK) loadB(kc + 1, bufB);
            doChunk(kc, bufA);
            if (++kc >= NCHK) break;
            if (kc + 1 < NCHK) loadB(kc + 1, bufA);
            doChunk(kc, bufB);
            if (++kc >= NCHK) break;
        }
    }
    __syncthreads();    // strip free for A1 overlay

    // ---------------- epilogues (round-13, unchanged) ----------------
    if (MODE == 0){
        #pragma unroll
        for (int mt = 0; mt < 2; ++mt)
        #pragma unroll
        for (int half = 0; half < 2; ++half){
            int p = w*32 + mt*16 + r + 8*half;
            int hwp = (by0 + (p>>4))*Wn + bx0 + (p&15);
            #pragma unroll
            for (int nt = 0; nt < 8; ++nt){
                int col = nt*8 + cq*2;
                float v0 = half ? acc[mt][nt].z : acc[mt][nt].x;
                float v1 = half ? acc[mt][nt].w : acc[mt][nt].y;
                if (nt < 4){
                    o0[((size_t)(b*32 + col  ))*HWn + hwp] = sigmoidf_(v0 + __ldg(biasA + col));
                    o0[((size_t)(b*32 + col+1))*HWn + hwp] = sigmoidf_(v1 + __ldg(biasA + col+1));
                } else {
                    int oc = col - 32;
                    size_t i0 = ((size_t)(b*32 + oc  ))*HWn + hwp;
                    size_t i1 = ((size_t)(b*32 + oc+1))*HWn + hwp;
                    A1[p*33 + oc  ] = sigmoidf_(v0 + __ldg(biasB + oc  )) * __ldg(hidden + i0);
                    A1[p*33 + oc+1] = sigmoidf_(v1 + __ldg(biasB + oc+1)) * __ldg(hidden + i1);
                }
            }
        }
        __syncthreads();
        {
            int p = tid;
            size_t g = (size_t)b*HWn + (by0 + (p>>4))*Wn + bx0 + (p&15);
            char* dst = g_p1 + g*320;
            #pragma unroll
            for (int u = 0; u < 4; ++u){
                __half hs[8], ls[8];
                #pragma unroll
                for (int i = 0; i < 8; ++i){
                    float v = A1[p*33 + u*8 + i];
                    __half h = __float2half_rn(v);
                    hs[i] = h;
                    ls[i] = __float2half_rn(v - __half2float(h));
                }
                *(uint4*)(dst + u*16)       = *(uint4*)hs;
                *(uint4*)(dst + 160 + u*16) = *(uint4*)ls;
            }
        }
    } else if (MODE == 1){
        #pragma unroll
        for (int mt = 0; mt < 2; ++mt)
        #pragma unroll
        for (int half = 0; half < 2; ++half){
            int p = w*32 + mt*16 + r + 8*half;
            int hwp = (by0 + (p>>4))*Wn + bx0 + (p&15);
            #pragma unroll
            for (int nt = 0; nt < 4; ++nt){
                int col = nt*8 + cq*2;
                float v0 = half ? acc[mt][nt].z : acc[mt][nt].x;
                float v1 = half ? acc[mt][nt].w : acc[mt][nt].y;
                float q0 = tanhf(v0 + __ldg(biasA + col));
                float q1 = tanhf(v1 + __ldg(biasA + col+1));
                size_t i0 = ((size_t)(b*32 + col  ))*HWn + hwp;
                size_t i1 = ((size_t)(b*32 + col+1))*HWn + hwp;
                float z0 = g_z[i0], z1 = g_z[i1];
                float h0 = (1.f - z0)*__ldg(hidden + i0) + z0*q0;
                float h1 = (1.f - z1)*__ldg(hidden + i1) + z1*q1;
                o0[i0] = h0;
                o0[i1] = h1;
                A1[p*33 + col  ] = h0;
                A1[p*33 + col+1] = h1;
            }
        }
        __syncthreads();
        {
            int p = tid;
            size_t g = (size_t)b*HWn + (by0 + (p>>4))*Wn + bx0 + (p&15);
            char* dst = g_p2 + g*128;
            #pragma unroll
            for (int u = 0; u < 4; ++u){
                __half hs[8], ls[8];
                #pragma unroll
                for (int i = 0; i < 8; ++i){
                    float v = A1[p*33 + u*8 + i];
                    __half h = __float2half_rn(v);
                    hs[i] = h;
                    ls[i] = __float2half_rn(v - __half2float(h));
                }
                *(uint4*)(dst + u*16)      = *(uint4*)hs;
                *(uint4*)(dst + 64 + u*16) = *(uint4*)ls;
            }
        }
    } else {
        float cb = __ldg(ch2b);
        float ps[2][2] = {{0.f,0.f},{0.f,0.f}};
        #pragma unroll
        for (int mt = 0; mt < 2; ++mt)
        #pragma unroll
        for (int half = 0; half < 2; ++half){
            int p = w*32 + mt*16 + r + 8*half;
            #pragma unroll
            for (int nt = 0; nt < 8; ++nt){
                int col = nt*8 + cq*2;
                float v0 = half ? acc[mt][nt].z : acc[mt][nt].x;
                float v1 = half ? acc[mt][nt].w : acc[mt][nt].y;
                v0 = fmaxf(v0, 0.f);
                v1 = fmaxf(v1, 0.f);
                if (nt < 4){
                    A1[p*33 + col  ] = v0;
                    A1[p*33 + col+1] = v1;
                } else {
                    ps[mt][half] = fmaf(v0, __ldg(ch2w + col-32),
                                   fmaf(v1, __ldg(ch2w + col-31), ps[mt][half]));
                }
            }
        }
        #pragma unroll
        for (int mt = 0; mt < 2; ++mt)
        #pragma unroll
        for (int half = 0; half < 2; ++half){
            float pp = ps[mt][half];
            pp += __shfl_xor_sync(0xffffffffu, pp, 1);
            pp += __shfl_xor_sync(0xffffffffu, pp, 2);
            if (cq == 0){
                int p = w*32 + mt*16 + r + 8*half;
                size_t g = (size_t)b*HWn + (by0 + (p>>4))*Wn + bx0 + (p&15);
                float cs = cb + pp;
                o2[g] = cs;
                o1[g] = sigmoidf_(cs);
            }
        }
        __syncthreads();
        float a[32];
        #pragma unroll
        for (int ic = 0; ic < 32; ++ic) a[ic] = A1[tid*33 + ic];
        float t2[64];
        #pragma unroll
        for (int i = 0; i < 64; ++i) t2[i] = 0.f;
        #pragma unroll
        for (int ic = 0; ic < 32; ++ic){
            float vv = a[ic];
            const float4* wr = (const float4*)(dh2s + ic*64);
            #pragma unroll
            for (int q4 = 0; q4 < 16; ++q4){
                float4 w4 = wr[q4];
                t2[q4*4+0] = fmaf(vv, w4.x, t2[q4*4+0]);
                t2[q4*4+1] = fmaf(vv, w4.y, t2[q4*4+1]);
                t2[q4*4+2] = fmaf(vv, w4.z, t2[q4*4+2]);
                t2[q4*4+3] = fmaf(vv, w4.w, t2[q4*4+3]);
            }
        }
        size_t g = (size_t)b*HWn + (by0 + (tid>>4))*Wn + bx0 + (tid&15);
        char* dst = g_t2h + g*256;
        #pragma unroll
        for (int u = 0; u < 8; ++u){
            __half hs[8], ls[8];
            #pragma unroll
            for (int i = 0; i < 8; ++i){
                float v = fmaxf(t2[u*8 + i], 0.f);
                __half h = __float2half_rn(v);
                hs[i] = h;
                ls[i] = __float2half_rn(v - __half2float(h));
            }
            *(uint4*)(dst + u*16)       = *(uint4*)hs;
            *(uint4*)(dst + 128 + u*16) = *(uint4*)ls;
        }
    }
}

// ---------------- softmax head v2 + coalesced prob store ----------------------
__global__ void __launch_bounds__(256) softmax_head(
    const float* __restrict__ b3,
    float* __restrict__ prob,
    float* __restrict__ nd)
{
    extern __shared__ char sm[];
    char*  t2s  = sm;                          // 64 x 272B
    char*  bbuf = sm + 17408;                  // 2 x 24576
    float* b3s  = (float*)(sm + 66560);        // 256
    float* rs_s = (float*)(sm + 67584);        // 64
    float* logits = (float*)sm;                // overlay: 64 x 260 fp32

    int tid = threadIdx.x, lane = tid & 31, w = tid >> 5;
    int g0 = blockIdx.x * 64;
    int b  = g0 / HWn, hw0 = g0 - b*HWn;

    {
        const uint4* src = (const uint4*)(g_t2h + (size_t)g0*256);
        #pragma unroll
        for (int e = tid; e < 1024; e += 256){
            int p = e >> 4, u = e & 15;
            *(uint4*)(t2s + p*272 + u*16) = __ldg(src + e);
        }
    }
    b3s[tid] = b3[tid];

    auto stageB = [&](int kc, int s){
        const __half* base = g_w3 + kc*8192;
        char* dst = bbuf + s*24576;
        #pragma unroll
        for (int e = tid; e < 1024; e += 256){
            int hl = e >> 9, rem = e & 511, n = rem >> 1, part = rem & 1;
            uint4 v = *(const uint4*)(base + hl*4096 + n*16 + part*8);
            *(uint4*)(dst + hl*12288 + n*48 + part*16) = v;
        }
    };
    stageB(0, 0);
    stageB(1, 1);
    __syncthreads();

    int mi = w >> 1, ng = w & 1;
    uint32_t t2S = smem_u32(t2s);
    uint32_t bS  = smem_u32(bbuf);

    float4 acc[16];
    #pragma unroll
    for (int i = 0; i < 16; ++i) acc[i] = make_float4(0.f,0.f,0.f,0.f);

    #pragma unroll
    for (int ck = 0; ck < 4; ++ck){
        uint32_t slot = bS + (uint32_t)(ck & 1)*24576;
        int rowA = mi*16 + (lane & 15);
        uint32_t aoff = t2S + (uint32_t)(rowA*272 + ck*32) + ((uint32_t)(lane>>4) << 4);
        uint32_t ah[4], al[4];
        ldm_x4(ah, aoff);
        ldm_x4(al, aoff + 128);
        #pragma unroll
        for (int nt16 = 0; nt16 < 8; ++nt16){
            int rowB = ng*128 + nt16*16 + (lane & 7) + ((lane >> 4) << 3);
            uint32_t boff = slot + (uint32_t)(rowB*48 + ((lane >> 3) & 1)*16);
            uint32_t bh[4], bl[4];
            ldm_x4(bh, boff);
            ldm_x4(bl, boff + 12288);
            // interleaved: per-acc order stays hh -> hl -> lh (bit-identical),
            // dependent distance 2 instead of 1
            mma16(acc[nt16*2  ], ah, bh[0], bh[1]);
            mma16(acc[nt16*2+1], ah, bh[2], bh[3]);
            mma16(acc[nt16*2  ], ah, bl[0], bl[1]);
            mma16(acc[nt16*2+1], ah, bl[2], bl[3]);
            mma16(acc[nt16*2  ], al, bh[0], bh[1]);
            mma16(acc[nt16*2+1], al, bh[2], bh[3]);
        }
        __syncthreads();
        if (ck + 2 < 4) stageB(ck + 2, ck & 1);
    }

    {
        int r = lane >> 2, cq = lane & 3;
        #pragma unroll
        for (int nt = 0; nt < 16; ++nt){
            int col = ng*128 + nt*8 + cq*2;
            int row0 = mi*16 + r;
            float bb0 = b3s[col], bb1 = b3s[col+1];
            logits[row0*260 + col]     = acc[nt].x + bb0;
            logits[row0*260 + col+1]   = acc[nt].y + bb1;
            logits[(row0+8)*260 + col]   = acc[nt].z + bb0;
            logits[(row0+8)*260 + col+1] = acc[nt].w + bb1;
        }
    }
    __syncthreads();

    int px = (w << 3) + (lane >> 2);
    int cg = lane & 3;
    float* lrow = logits + px*260 + cg;

    float m = -3.4e38f; int am = 255;
    #pragma unroll
    for (int j = 0; j < 64; ++j){
        float v = lrow[j*4];
        int oc = cg + j*4;
        if (v > m || (v == m && oc < am)) { m = v; am = oc; }
    }
    #pragma unroll
    for (int d = 1; d < 4; d <<= 1){
        float om = __shfl_xor_sync(0xffffffffu, m, d);
        int   oa = __shfl_xor_sync(0xffffffffu, am, d);
        if (om > m || (om == m && oa < am)) { m = om; am = oa; }
    }

    float s = 0.f;
    #pragma unroll
    for (int j = 0; j < 64; ++j){
        float e = __expf(lrow[j*4] - m);
        lrow[j*4] = e;
        s += e;
    }
    #pragma unroll
    for (int d = 1; d < 4; d <<= 1) s += __shfl_xor_sync(0xffffffffu, s, d);
    float rS = 1.f / s;

    int lo = am - 4, hi = am + 4;
    int ocl = lo < 0 ? 0 : lo;
    int och = hi > 255 ? 255 : hi;
    float num = 0.f, den = 0.f;
    #pragma unroll
    for (int j = 0; j < 64; ++j){
        int oc = cg + j*4;
        if (oc >= ocl && oc <= och){
            float pv = lrow[j*4] * rS;
            float mult = 1.f;
            if (oc == 0   && lo < 0)   mult += (float)(-lo);
            if (oc == 255 && hi > 255) mult += (float)(hi - 255);
            num = fmaf(mult * (float)oc, pv, num);
            den = fmaf(mult, pv, den);
        }
    }
    #pragma unroll
    for (int d = 1; d < 4; d <<= 1){
        num += __shfl_xor_sync(0xffffffffu, num, d);
        den += __shfl_xor_sync(0xffffffffu, den, d);
    }
    if (cg == 0){
        nd[g0 + px] = (num / (1e-6f + den)) * (1.0f / 255.0f);
        rs_s[px] = rS;
    }
    __syncthreads();

    {
        float* pbase = prob + (size_t)b*NSn*HWn + hw0;
        #pragma unroll 8
        for (int e = tid; e < 16384; e += 256){
            int oc2 = e >> 6, p2 = e & 63;
            pbase[(size_t)oc2*HWn + p2] = logits[p2*260 + oc2] * rs_s[p2];
        }
    }
}

// ---------------- launch ------------------------------------------------------
extern "C" void kernel_launch(void* const* d_in, const int* in_sizes, int n_in,
                              void* d_out, int out_size)
{
    const float* hidden  = (const float*)d_in[0];
    const float* ndep    = (const float*)d_in[1];
    const float* corr    = (const float*)d_in[2];
    const float* convz_w = (const float*)d_in[3];
    const float* convz_b = (const float*)d_in[4];
    const float* convr_w = (const float*)d_in[5];
    const float* convr_b = (const float*)d_in[6];
    const float* convq_w = (const float*)d_in[7];
    const float* convq_b = (const float*)d_in[8];
    const float* dh1_w   = (const float*)d_in[9];
    const float* dh2_w   = (const float*)d_in[10];
    const float* dh3_w   = (const float*)d_in[11];
    const float* dh3_b   = (const float*)d_in[12];
    const float* ch1_w   = (const float*)d_in[13];
    const float* ch2_w   = (const float*)d_in[14];
    const float* ch2_b   = (const float*)d_in[15];

    float* out = (float*)d_out;
    float* out_h     = out;
    float* out_nd    = out_h  + (size_t)NPIX*32;
    float* out_prob  = out_nd + NPIX;
    float* out_conf  = out_prob + (size_t)NPIX*256;
    float* out_conf0 = out_conf + NPIX;

    float* zbuf;  cudaGetSymbolAddress((void**)&zbuf,  g_z);

    const int SMEM_M0 = 10*18*336;               // 60480
    const int SMEM_M1 = 10*18*336;               // 60480
    const int SMEM_M2 = 12*20*144 + 8192;        // 42752
    const int SMEM_SMAX = 66560 + 1024 + 256;    // 67840

    cudaFuncSetAttribute(conv_mma<0>, cudaFuncAttributeMaxDynamicSharedMemorySize, SMEM_M0);
    cudaFuncSetAttribute(conv_mma<1>, cudaFuncAttributeMaxDynamicSharedMemorySize, SMEM_M1);
    cudaFuncSetAttribute(conv_mma<2>, cudaFuncAttributeMaxDynamicSharedMemorySize, SMEM_M2);
    cudaFuncSetAttribute(softmax_head, cudaFuncAttributeMaxDynamicSharedMemorySize, SMEM_SMAX);

    prep_inputs<<<NPIX/128, 128>>>(hidden, ndep, corr);
    prep_weights<<<(191488 + 255)/256, 256>>>(convz_w, convr_w, convq_w, dh1_w, ch1_w, dh3_w);

    dim3 blk(128);
    dim3 grd(Wn/16, Hn/8, Bn);

    conv_mma<0><<<grd, blk, SMEM_M0>>>(convz_b, convr_b, hidden,
                                       nullptr, nullptr, nullptr,
                                       zbuf, nullptr, nullptr);
    conv_mma<1><<<grd, blk, SMEM_M1>>>(convq_b, nullptr, hidden,
                                       nullptr, nullptr, nullptr,
                                       out_h, nullptr, nullptr);
    conv_mma<2><<<grd, blk, SMEM_M2>>>(nullptr, nullptr, nullptr,
                                       dh2_w, ch2_w, ch2_b,
                                       nullptr, out_conf, out_conf0);
    softmax_head<<<NPIX/64, 256, SMEM_SMAX>>>(dh3_b, out_prob, out_nd);
}